// round 6
// baseline (speedup 1.0000x reference)
#include <cuda_runtime.h>

#define NS   1024
#define NB   16
#define NQ   8192
#define NDV  64
#define G    16
#define NC   (G * G)
#define QB   256

// Scratch (allocation-free rule: __device__ globals).
__device__ float4 g_sorted[NB][NS];          // (-2sx, -2sy, s2, idx-bits), cell-sorted
__device__ int    g_cellStart[NB][NC + 1];
__device__ float4 g_qsorted[NB][NQ];         // (qx, qy, q2, orig-idx-bits), cell-sorted
__device__ int    g_qcnt[NB][NC];            // zero at module load; re-zeroed by K2 each run
__device__ int    g_qcur[NB][NC];

#define QCNT_BLOCKS (NQ * NB / 256)          // 512

// ---------------------------------------------------------------------------
// K1 (fused): blocks 0..15 bin samples; blocks 16.. count query cells.
// ---------------------------------------------------------------------------
__global__ __launch_bounds__(256)
void k1_bin_and_count(const float* __restrict__ sample_posns,   // [NS, NB, 2]
                      const float* __restrict__ query_posns)    // [NQ, NB, 2]
{
    const int tid = threadIdx.x;

    if (blockIdx.x >= NB) {
        // ---- query cell counting ----
        const int j = (blockIdx.x - NB) * 256 + tid;   // j = q*NB + b
        const float2 p = *reinterpret_cast<const float2*>(query_posns + 2 * j);
        const int b = j & (NB - 1);
        int cx = (int)(p.x * G); cx = cx < 0 ? 0 : (cx > G - 1 ? G - 1 : cx);
        int cy = (int)(p.y * G); cy = cy < 0 ? 0 : (cy > G - 1 ? G - 1 : cy);
        atomicAdd(&g_qcnt[b][cy * G + cx], 1);
        return;
    }

    // ---- sample binning (one block per batch) ----
    __shared__ int s_cnt[NC];
    __shared__ int s_warp[8];
    __shared__ int s_cur[NC];

    const int b    = blockIdx.x;
    const int lane = tid & 31;
    const int wid  = tid >> 5;

    s_cnt[tid] = 0;
    __syncthreads();

    float2 p[4];
    int    cell[4];
#pragma unroll
    for (int k = 0; k < 4; k++) {
        const int s = tid + k * 256;
        p[k] = *reinterpret_cast<const float2*>(sample_posns + (s * NB + b) * 2);
        int cx = (int)(p[k].x * G); cx = cx < 0 ? 0 : (cx > G - 1 ? G - 1 : cx);
        int cy = (int)(p[k].y * G); cy = cy < 0 ? 0 : (cy > G - 1 ? G - 1 : cy);
        cell[k] = cy * G + cx;
        atomicAdd(&s_cnt[cell[k]], 1);
    }
    __syncthreads();

    const int cnt = s_cnt[tid];
    int incl = cnt;
#pragma unroll
    for (int ofs = 1; ofs < 32; ofs <<= 1) {
        const int t = __shfl_up_sync(0xffffffffu, incl, ofs);
        if (lane >= ofs) incl += t;
    }
    if (lane == 31) s_warp[wid] = incl;
    __syncthreads();
    if (wid == 0 && lane < 8) {
        int w = s_warp[lane];
#pragma unroll
        for (int ofs = 1; ofs < 8; ofs <<= 1) {
            const int t = __shfl_up_sync(0xffu, w, ofs);
            if (lane >= ofs) w += t;
        }
        s_warp[lane] = w;
    }
    __syncthreads();
    const int excl = incl - cnt + (wid > 0 ? s_warp[wid - 1] : 0);

    s_cur[tid] = excl;
    g_cellStart[b][tid] = excl;
    if (tid == 0) g_cellStart[b][NC] = NS;
    __syncthreads();

#pragma unroll
    for (int k = 0; k < 4; k++) {
        const int s   = tid + k * 256;
        const int pos = atomicAdd(&s_cur[cell[k]], 1);
        // s2 with reference rounding: mul, mul, add. -2 fold is bit-exact (pow2 scale).
        const float s2 = __fadd_rn(__fmul_rn(p[k].x, p[k].x), __fmul_rn(p[k].y, p[k].y));
        g_sorted[b][pos] = make_float4(-2.0f * p[k].x, -2.0f * p[k].y, s2, __int_as_float(s));
    }
}

// ---------------------------------------------------------------------------
// K2: per-batch exclusive scan of query cell counts -> g_qcur; re-zero counts.
// ---------------------------------------------------------------------------
__global__ __launch_bounds__(256)
void k2_scan_qcells()
{
    __shared__ int s_warp[8];
    const int tid  = threadIdx.x;
    const int b    = blockIdx.x;
    const int lane = tid & 31;
    const int wid  = tid >> 5;

    const int cnt = g_qcnt[b][tid];
    g_qcnt[b][tid] = 0;                       // restore invariant for next replay
    int incl = cnt;
#pragma unroll
    for (int ofs = 1; ofs < 32; ofs <<= 1) {
        const int t = __shfl_up_sync(0xffffffffu, incl, ofs);
        if (lane >= ofs) incl += t;
    }
    if (lane == 31) s_warp[wid] = incl;
    __syncthreads();
    if (wid == 0 && lane < 8) {
        int w = s_warp[lane];
#pragma unroll
        for (int ofs = 1; ofs < 8; ofs <<= 1) {
            const int t = __shfl_up_sync(0xffu, w, ofs);
            if (lane >= ofs) w += t;
        }
        s_warp[lane] = w;
    }
    __syncthreads();
    g_qcur[b][tid] = incl - cnt + (wid > 0 ? s_warp[wid - 1] : 0);
}

// ---------------------------------------------------------------------------
// K3: scatter queries into cell-sorted order with q2 precomputed.
// ---------------------------------------------------------------------------
__global__ __launch_bounds__(256)
void k3_scatter_queries(const float* __restrict__ query_posns)
{
    const int j = blockIdx.x * 256 + threadIdx.x;   // j = q*NB + b
    const float2 p = *reinterpret_cast<const float2*>(query_posns + 2 * j);
    const int b = j & (NB - 1);
    const int q = j >> 4;
    int cx = (int)(p.x * G); cx = cx < 0 ? 0 : (cx > G - 1 ? G - 1 : cx);
    int cy = (int)(p.y * G); cy = cy < 0 ? 0 : (cy > G - 1 ? G - 1 : cy);
    const int slot = atomicAdd(&g_qcur[b][cy * G + cx], 1);
    const float q2 = __fadd_rn(__fmul_rn(p.x, p.x), __fmul_rn(p.y, p.y));
    g_qsorted[b][slot] = make_float4(p.x, p.y, q2, __int_as_float(q));
}

// ---------------------------------------------------------------------------
// K4: exact 1-NN on cell-sorted queries (convergent warps), then gather.
// ---------------------------------------------------------------------------
__device__ __forceinline__ void scan_range(const float4* __restrict__ samp,
                                           int s0, int s1,
                                           float qx, float qy, float q2,
                                           float& best, int& bi)
{
    for (int k = s0; k < s1; k++) {
        const float4 v = samp[k];
        // EXACT reference rounding: t = fma(qy,-2sy, qx*(-2sx)); d = (q2 + t) + s2
        const float t = __fmaf_rn(qy, v.y, __fmul_rn(qx, v.x));
        const float d = __fadd_rn(__fadd_rn(q2, t), v.z);
        const int idx = __float_as_int(v.w);
        if (d < best || (d == best && idx < bi)) { best = d; bi = idx; }
    }
}

__global__ __launch_bounds__(QB)
void nn_query_kernel(const float* __restrict__ sample_vals,   // [NS, NB, NDV]
                     float* __restrict__ out)                 // [NQ, NB, NDV]
{
    __shared__ float4 s_samp[NS];        // 16 KB
    __shared__ int    s_cs[NC + 1];
    __shared__ int    bidx_sh[QB];
    __shared__ int    orig_sh[QB];

    const int tid   = threadIdx.x;
    const int b     = blockIdx.y;
    const int qbase = blockIdx.x * QB;

    // Stage batch samples + cell offsets into SMEM (coalesced).
#pragma unroll
    for (int i = tid; i < NS; i += QB) s_samp[i] = g_sorted[b][i];
    if (tid < NC) s_cs[tid] = g_cellStart[b][tid];
    if (tid == 0) s_cs[NC] = NS;

    // Cell-sorted query: lanes of a warp share (nearly) the same cell.
    const float4 qs = g_qsorted[b][qbase + tid];
    const float qx = qs.x, qy = qs.y, q2 = qs.z;
    const int   orig = __float_as_int(qs.w);

    int cx = (int)(qx * G); cx = cx < 0 ? 0 : (cx > G - 1 ? G - 1 : cx);
    int cy = (int)(qy * G); cy = cy < 0 ? 0 : (cy > G - 1 ? G - 1 : cy);

    __syncthreads();

    float best = __int_as_float(0x7f800000);  // +inf
    int   bi   = NS;
    const float h = 1.0f / G;

    // Initial 3x3 region: 3 row-contiguous ranges (cell-sorted order).
    {
        const int x0 = max(0, cx - 1), x1 = min(G - 1, cx + 1);
        const int y0 = max(0, cy - 1), y1 = min(G - 1, cy + 1);
        for (int yy = y0; yy <= y1; yy++)
            scan_range(s_samp, s_cs[yy * G + x0], s_cs[yy * G + x1 + 1], qx, qy, q2, best, bi);
    }

    // Ring expansion until the geometric bound certifies the winner (rare).
    int r = 1;
    while (true) {
        float db = 3.4e38f;
        if (cx - r > 0)     db = fminf(db, qx - (float)(cx - r) * h);
        if (cx + r < G - 1) db = fminf(db, (float)(cx + r + 1) * h - qx);
        if (cy - r > 0)     db = fminf(db, qy - (float)(cy - r) * h);
        if (cy + r < G - 1) db = fminf(db, (float)(cy + r + 1) * h - qy);
        if (best < db * db - 1e-5f) break;  // margin > total rounding error (~1e-6)
        if (cx - r <= 0 && cx + r >= G - 1 && cy - r <= 0 && cy + r >= G - 1) break;
        r++;
        const int nx0 = cx - r, nx1 = cx + r, ny0 = cy - r, ny1 = cy + r;
        const int xs = max(0, nx0), xe = min(G - 1, nx1);
        if (ny0 >= 0)
            scan_range(s_samp, s_cs[ny0 * G + xs], s_cs[ny0 * G + xe + 1], qx, qy, q2, best, bi);
        if (ny1 <= G - 1)
            scan_range(s_samp, s_cs[ny1 * G + xs], s_cs[ny1 * G + xe + 1], qx, qy, q2, best, bi);
        const int ys = max(0, ny0 + 1), ye = min(G - 1, ny1 - 1);
        if (nx0 >= 0)
            for (int yy = ys; yy <= ye; yy++)
                scan_range(s_samp, s_cs[yy * G + nx0], s_cs[yy * G + nx0 + 1], qx, qy, q2, best, bi);
        if (nx1 <= G - 1)
            for (int yy = ys; yy <= ye; yy++)
                scan_range(s_samp, s_cs[yy * G + nx1], s_cs[yy * G + nx1 + 1], qx, qy, q2, best, bi);
    }

    bidx_sh[tid] = bi;
    orig_sh[tid] = orig;
    __syncthreads();

    // Cooperative gather of winning value rows; scatter to original query rows.
    const float4* __restrict__ sv4  = reinterpret_cast<const float4*>(sample_vals);
    float4* __restrict__       out4 = reinterpret_cast<float4*>(out);
    const int V4 = NDV / 4;  // 16

#pragma unroll
    for (int item = tid; item < QB * V4; item += QB) {
        const int j = item >> 4;
        const int v = item & (V4 - 1);
        const int s  = bidx_sh[j];
        const int oq = orig_sh[j];
        out4[(oq * NB + b) * V4 + v] = sv4[(s * NB + b) * V4 + v];
    }
}

extern "C" void kernel_launch(void* const* d_in, const int* in_sizes, int n_in,
                              void* d_out, int out_size)
{
    const float* sample_vals  = (const float*)d_in[0];  // [1024, 16, 64]
    const float* sample_posns = (const float*)d_in[1];  // [1024, 16, 2]
    const float* query_posns  = (const float*)d_in[2];  // [8192, 16, 2]
    float* out = (float*)d_out;                          // [8192, 16, 64]

    k1_bin_and_count<<<NB + QCNT_BLOCKS, 256>>>(sample_posns, query_posns);
    k2_scan_qcells<<<NB, 256>>>();
    k3_scatter_queries<<<NQ * NB / 256, 256>>>(query_posns);

    dim3 grid(NQ / QB, NB);  // (32, 16)
    nn_query_kernel<<<grid, QB>>>(sample_vals, out);
}